// round 12
// baseline (speedup 1.0000x reference)
#include <cuda_runtime.h>
#include <cstdint>

// Problem constants (fixed-shape problem)
#define WIN   48
#define DIN   64
#define DOUT  128
#define BATCH 4096
#define NSEG  (BATCH * WIN)      // 196608 segments
#define CAP   64                 // bucket slots per segment

#define A_PAD 68                 // means row stride: banks 4g+tig bijective
#define W_PAD 136                // W row stride: banks 8tig+g bijective

// Scratch
__device__ int      g_cur[NSEG];
__device__ int      g_bucket[NSEG * CAP];
__device__ float    g_mean[NSEG * DIN];
__device__ uint32_t g_whi[DIN * DOUT];   // tf32 hi plane of W
__device__ uint32_t g_wlo[DIN * DOUT];   // tf32 lo plane of W

__device__ __forceinline__ uint32_t tf32_bits(float x) {
    uint32_t u;
    asm("cvt.rna.tf32.f32 %0, %1;" : "=r"(u) : "f"(x));
    return u;
}
__device__ __forceinline__ void mma_tf32(float* c, const uint32_t* a,
                                         const uint32_t* b) {
    asm("mma.sync.aligned.m16n8k8.row.col.f32.tf32.tf32.f32 "
        "{%0,%1,%2,%3}, {%4,%5,%6,%7}, {%8,%9}, {%0,%1,%2,%3};"
        : "+f"(c[0]), "+f"(c[1]), "+f"(c[2]), "+f"(c[3])
        : "r"(a[0]), "r"(a[1]), "r"(a[2]), "r"(a[3]), "r"(b[0]), "r"(b[1]));
}

// ---------------------------------------------------------------------------
// 0) split W into tf32 hi/lo planes (once; W is batch-invariant)
// ---------------------------------------------------------------------------
__global__ void wsplit_kernel(const float* __restrict__ Wm) {
    int i = blockIdx.x * blockDim.x + threadIdx.x;
    if (i < DIN * DOUT) {
        float w = Wm[i];
        uint32_t hi = tf32_bits(w);
        g_whi[i] = hi;
        g_wlo[i] = tf32_bits(w - __uint_as_float(hi));
    }
}

// ---------------------------------------------------------------------------
// 1) zero cursors
// ---------------------------------------------------------------------------
__global__ void zero_cur_kernel() {
    int i = blockIdx.x * blockDim.x + threadIdx.x;
    if (i < NSEG) g_cur[i] = 0;
}

// ---------------------------------------------------------------------------
// 2) scatter event indices into fixed-capacity buckets (bump allocation)
// ---------------------------------------------------------------------------
__global__ void scatter_idx_kernel(const int* __restrict__ bi,
                                   const int* __restrict__ wi, int n) {
    int i = blockIdx.x * blockDim.x + threadIdx.x;
    if (i >= n) return;
    int seg = bi[i] * WIN + wi[i];
    int pos = atomicAdd(&g_cur[seg], 1);
    if (pos < CAP) g_bucket[(seg << 6) + pos] = i;
}

// ---------------------------------------------------------------------------
// 3) gather-reduce: ONE warp per segment, burst loads (unchanged; known-good)
// ---------------------------------------------------------------------------
__global__ __launch_bounds__(256) void reduce_kernel(const float* __restrict__ in) {
    int seg  = (blockIdx.x * blockDim.x + threadIdx.x) >> 5;
    int lane = threadIdx.x & 31;
    if (seg >= NSEG) return;

    int cnt = __ldg(&g_cur[seg]);
    if (cnt > CAP) cnt = CAP;
    float* dst = g_mean + (size_t)seg * DIN + lane * 2;
    if (cnt == 0) {
        dst[0] = 0.f;
        dst[1] = 0.f;
        return;
    }
    int base = seg << 6;
    int last = cnt - 1;

    int idx[16];
    #pragma unroll
    for (int t = 0; t < 16; t++)
        idx[t] = __ldg(&g_bucket[base + (t < last ? t : last)]);

    float2 v[16];
    #pragma unroll
    for (int t = 0; t < 16; t++) {
        v[t] = make_float2(0.f, 0.f);
        if (t < cnt)
            v[t] = *reinterpret_cast<const float2*>(
                in + (size_t)idx[t] * DIN + lane * 2);
    }

    float a0 = 0.f, a1 = 0.f;
    #pragma unroll
    for (int t = 0; t < 16; t += 4) {
        a0 += (v[t].x + v[t+1].x) + (v[t+2].x + v[t+3].x);
        a1 += (v[t].y + v[t+1].y) + (v[t+2].y + v[t+3].y);
    }

    for (int t = 16; t < cnt; t++) {
        int e = __ldg(&g_bucket[base + t]);
        float2 w = *reinterpret_cast<const float2*>(
            in + (size_t)e * DIN + lane * 2);
        a0 += w.x;
        a1 += w.y;
    }

    float inv = 1.f / (float)cnt;
    dst[0] = a0 * inv;
    dst[1] = a1 * inv;
}

// ---------------------------------------------------------------------------
// 4) per-batch GEMM on tensor cores, 3xTF32, all conversions hoisted.
//    Dynamic smem layout (bytes):
//      s_whi [64*136] u32   @ 0        (34816)
//      s_wlo [64*136] u32   @ 34816    (34816)
//      s_a   [48*68]  f32/u32 hi-in-place @ 69632 (13056)
//      s_alo [48*68]  u32   @ 82688    (13056)
//      s_b   [128]    f32   @ 95744
//      s_has [48]     f32   @ 96256
//    Out staging reuses the s_whi/s_wlo region after the mainloop.
// ---------------------------------------------------------------------------
#define SMEM_TOTAL (96256 + 256)

__global__ __launch_bounds__(256) void pool_gemm_kernel(
    const float* __restrict__ Wm,     // unused (split planes used instead)
    const float* __restrict__ bias,
    float*       __restrict__ out)    // [BATCH][DOUT][WIN]
{
    extern __shared__ char smem[];
    uint32_t* s_whi = reinterpret_cast<uint32_t*>(smem);
    uint32_t* s_wlo = s_whi + DIN * W_PAD;
    float*    s_a   = reinterpret_cast<float*>(s_wlo + DIN * W_PAD);
    uint32_t* s_ahi = reinterpret_cast<uint32_t*>(s_a);
    uint32_t* s_alo = reinterpret_cast<uint32_t*>(s_a + WIN * A_PAD);
    float*    s_b   = reinterpret_cast<float*>(s_alo + WIN * A_PAD);
    float*    s_has = s_b + DOUT;
    float*    s_out = reinterpret_cast<float*>(smem);   // staging [128][49]

    int b   = blockIdx.x;
    int tid = threadIdx.x;
    int lane = tid & 31;
    int wg   = tid >> 5;
    int g    = lane >> 2;     // group id 0..7
    int tig  = lane & 3;      // thread in group 0..3

    if (tid < WIN) s_has[tid] = (g_cur[b * WIN + tid] > 0) ? 1.f : 0.f;
    if (tid < DOUT) s_b[tid] = bias[tid];

    // ---- load precomputed W hi/lo planes into padded smem ----
    {
        const uint4* h4 = reinterpret_cast<const uint4*>(g_whi);
        const uint4* l4 = reinterpret_cast<const uint4*>(g_wlo);
        #pragma unroll
        for (int i = tid; i < DIN * DOUT / 4; i += 256) {
            int row = i >> 5;
            int c4  = i & 31;
            *reinterpret_cast<uint4*>(s_whi + row * W_PAD + c4 * 4) = h4[i];
            *reinterpret_cast<uint4*>(s_wlo + row * W_PAD + c4 * 4) = l4[i];
        }
    }
    // ---- load means into padded smem ----
    {
        const float4* m4 = reinterpret_cast<const float4*>(
            g_mean + (size_t)b * WIN * DIN);
        #pragma unroll
        for (int i = tid; i < WIN * DIN / 4; i += 256) {
            int row = i >> 4;
            int c4  = i & 15;
            *reinterpret_cast<float4*>(s_a + row * A_PAD + c4 * 4) = m4[i];
        }
    }
    __syncthreads();

    // ---- split A into tf32 hi (in place) / lo, once per element ----
    #pragma unroll
    for (int i = tid; i < WIN * DIN; i += 256) {
        int row = i >> 6;
        int col = i & 63;
        int a = row * A_PAD + col;
        float v = s_a[a];
        uint32_t hi = tf32_bits(v);
        s_ahi[a] = hi;
        s_alo[a] = tf32_bits(v - __uint_as_float(hi));
    }
    __syncthreads();

    // ---- accumulators: 3 m-tiles x 2 n-tiles x 4 ----
    float acc[3][2][4];
    #pragma unroll
    for (int mt = 0; mt < 3; mt++)
        #pragma unroll
        for (int nt = 0; nt < 2; nt++)
            #pragma unroll
            for (int q = 0; q < 4; q++) acc[mt][nt][q] = 0.f;

    int n0 = wg * 16;   // this warp's 16 output columns

    #pragma unroll
    for (int ks = 0; ks < 8; ks++) {
        int k0 = ks * 8;

        uint32_t ahi[3][4], alo[3][4];
        #pragma unroll
        for (int mt = 0; mt < 3; mt++) {
            int base = (mt * 16 + g) * A_PAD + k0 + tig;
            ahi[mt][0] = s_ahi[base];
            ahi[mt][1] = s_ahi[base + 8 * A_PAD];
            ahi[mt][2] = s_ahi[base + 4];
            ahi[mt][3] = s_ahi[base + 8 * A_PAD + 4];
            alo[mt][0] = s_alo[base];
            alo[mt][1] = s_alo[base + 8 * A_PAD];
            alo[mt][2] = s_alo[base + 4];
            alo[mt][3] = s_alo[base + 8 * A_PAD + 4];
        }

        uint32_t bhi[2][2], blo[2][2];
        #pragma unroll
        for (int nt = 0; nt < 2; nt++) {
            int base = (k0 + tig) * W_PAD + n0 + nt * 8 + g;
            bhi[nt][0] = s_whi[base];
            bhi[nt][1] = s_whi[base + 4 * W_PAD];
            blo[nt][0] = s_wlo[base];
            blo[nt][1] = s_wlo[base + 4 * W_PAD];
        }

        #pragma unroll
        for (int mt = 0; mt < 3; mt++)
            #pragma unroll
            for (int nt = 0; nt < 2; nt++) {
                mma_tf32(acc[mt][nt], ahi[mt], bhi[nt]);
                mma_tf32(acc[mt][nt], ahi[mt], blo[nt]);
                mma_tf32(acc[mt][nt], alo[mt], bhi[nt]);
            }
    }

    __syncthreads();   // all warps done reading W planes; reuse as staging

    // ---- stage results as out[d][w] pad-49 (+bias if nonempty) ----
    #pragma unroll
    for (int mt = 0; mt < 3; mt++) {
        int w0 = mt * 16 + g;
        int w1 = w0 + 8;
        float h0 = s_has[w0];
        float h1 = s_has[w1];
        #pragma unroll
        for (int nt = 0; nt < 2; nt++) {
            int d = n0 + nt * 8 + tig * 2;
            float bx = s_b[d], by = s_b[d + 1];
            s_out[(d    ) * 49 + w0] = acc[mt][nt][0] + h0 * bx;
            s_out[(d + 1) * 49 + w0] = acc[mt][nt][1] + h0 * by;
            s_out[(d    ) * 49 + w1] = acc[mt][nt][2] + h1 * bx;
            s_out[(d + 1) * 49 + w1] = acc[mt][nt][3] + h1 * by;
        }
    }
    __syncthreads();

    // ---- coalesced float4 store of out[b][d][w] ----
    float* obase = out + (size_t)b * DOUT * WIN;
    #pragma unroll
    for (int it = 0; it < 6; it++) {
        int j = it * 1024 + tid * 4;
        int d = j / 48;
        int w = j - d * 48;
        const float* src = s_out + d * 49 + w;
        float4 v = make_float4(src[0], src[1], src[2], src[3]);
        *reinterpret_cast<float4*>(obase + j) = v;
    }
}

// ---------------------------------------------------------------------------
extern "C" void kernel_launch(void* const* d_in, const int* in_sizes, int n_in,
                              void* d_out, int out_size) {
    const float* input = (const float*)d_in[0];
    const float* Wm    = (const float*)d_in[1];
    const float* bias  = (const float*)d_in[2];

    const int* bi;
    const int* wi;
    int n_events;
    if (n_in >= 6 && in_sizes[3] == 1) {
        bi = (const int*)d_in[4];
        wi = (const int*)d_in[5];
        n_events = in_sizes[4];
    } else {
        bi = (const int*)d_in[3];
        wi = (const int*)d_in[4];
        n_events = in_sizes[3];
    }

    int eb = (n_events + 255) / 256;

    static bool attr_set = false;
    if (!attr_set) {
        cudaFuncSetAttribute(pool_gemm_kernel,
                             cudaFuncAttributeMaxDynamicSharedMemorySize,
                             SMEM_TOTAL);
        attr_set = true;
    }

    wsplit_kernel<<<(DIN * DOUT + 255) / 256, 256>>>(Wm);
    zero_cur_kernel<<<(NSEG + 255) / 256, 256>>>();
    scatter_idx_kernel<<<eb, 256>>>(bi, wi, n_events);
    reduce_kernel<<<NSEG / 8, 256>>>(input);
    pool_gemm_kernel<<<BATCH, 256, SMEM_TOTAL>>>(Wm, bias, (float*)d_out);
}